// round 15
// baseline (speedup 1.0000x reference)
#include <cuda_runtime.h>
#include <cuda_bf16.h>
#include <cstdint>

#define B_   2
#define H_   8
#define G_   16
#define S_   2048
#define E_   64
#define DM   512
#define CT   32
#define CH   (S_/CT)
#define NCHAIN (B_*H_*G_)
#define REC  132
#define KCH  32
#define NCHUNK (DM/KCH)

// ---------------- fp32 scratch ----------------
__device__ float  g_qs[B_*H_*S_*E_];
__device__ float  g_kk[B_*H_*S_*E_];
__device__ float  g_vs[B_*H_*S_*E_];
__device__ float  g_cs[B_*H_*G_*E_];
__device__ float  g_scores[NCHAIN*S_];
__device__ float  g_wexp[NCHAIN*S_];
__device__ float  g_chunk[NCHAIN*CH*REC];
__device__ double g_partial[256];
__device__ float  g_mean;
__device__ int    g_ctr;

// ---------------- bf16 hi/lo buffers ----------------
__device__ uint4 g_qh4[262144], g_ql4[262144];
__device__ uint4 g_kh4[262144], g_kl4[262144];
__device__ uint4 g_vh4[262144], g_vl4[262144];
__device__ uint4 g_ch4[2048],   g_cl4[2048];
__device__ uint4 g_wqh4[32768], g_wql4[32768];
__device__ uint4 g_wkh4[32768], g_wkl4[32768];
__device__ uint4 g_wvh4[32768], g_wvl4[32768];
__device__ uint4 g_woh4[32768], g_wol4[32768];
__device__ uint4 g_wch4[32768], g_wcl4[32768];
__device__ uint4 g_ah4[262144], g_al4[262144];

// ---------------- helpers ----------------
static __device__ __forceinline__ uint32_t pack2(float a, float b) {
    __nv_bfloat162 t = __floats2bfloat162_rn(a, b);
    return *reinterpret_cast<uint32_t*>(&t);
}
static __device__ __forceinline__ void split1(float x, float& hi, float& lo) {
    __nv_bfloat16 h = __float2bfloat16_rn(x);
    hi = __bfloat162float(h);
    lo = x - hi;
}
static __device__ __forceinline__ void mma_bf16(float* c, const uint32_t* a, const uint32_t* b) {
    asm volatile(
        "mma.sync.aligned.m16n8k16.row.col.f32.bf16.bf16.f32 "
        "{%0,%1,%2,%3}, {%4,%5,%6,%7}, {%8,%9}, {%0,%1,%2,%3};"
        : "+f"(c[0]), "+f"(c[1]), "+f"(c[2]), "+f"(c[3])
        : "r"(a[0]), "r"(a[1]), "r"(a[2]), "r"(a[3]), "r"(b[0]), "r"(b[1]));
}
static __device__ __forceinline__ uint32_t smem_u32(const void* p) {
    uint32_t a;
    asm("{ .reg .u64 t; cvta.to.shared.u64 t, %1; cvt.u32.u64 %0, t; }" : "=r"(a) : "l"(p));
    return a;
}
static __device__ __forceinline__ void cpasync16(uint32_t dst, const void* src) {
    asm volatile("cp.async.cg.shared.global [%0], [%1], 16;" :: "r"(dst), "l"(src));
}
#define CP_COMMIT() asm volatile("cp.async.commit_group;" ::: "memory")
#define CP_WAIT1()  asm volatile("cp.async.wait_group 1;" ::: "memory")
static __device__ __forceinline__ void ldsm4(uint32_t* r, uint32_t addr) {
    asm volatile("ldmatrix.sync.aligned.m8n8.x4.shared.b16 {%0,%1,%2,%3}, [%4];"
        : "=r"(r[0]), "=r"(r[1]), "=r"(r[2]), "=r"(r[3]) : "r"(addr));
}

// ---------------- unified conversion (activations + transposed weights) ----
struct ConvSeg { const float* s; __nv_bfloat16* h; __nv_bfloat16* l; unsigned n4; };
struct Conv4 { ConvSeg seg[4]; };
struct WT5 { const float* w[5]; __nv_bfloat16* h[5]; __nv_bfloat16* l[5]; };

__global__ __launch_bounds__(256) void convert_all(
    Conv4 c, unsigned total4, unsigned actBlocks, WT5 wt)
{
    __shared__ float tile[32][33];
    if (blockIdx.x < actBlocks) {
        unsigned i = blockIdx.x * 256u + threadIdx.x;
        if (i >= total4) return;
        unsigned off = i;
#pragma unroll
        for (int s = 0; s < 4; s++) {
            unsigned n4 = c.seg[s].n4;
            if (off < n4) {
                float4 v = ((const float4*)c.seg[s].s)[off];
                float h0,h1,h2,h3,l0,l1,l2,l3;
                split1(v.x,h0,l0); split1(v.y,h1,l1); split1(v.z,h2,l2); split1(v.w,h3,l3);
                ((uint2*)c.seg[s].h)[off] = make_uint2(pack2(h0,h1), pack2(h2,h3));
                ((uint2*)c.seg[s].l)[off] = make_uint2(pack2(l0,l1), pack2(l2,l3));
                return;
            }
            off -= n4;
        }
    } else {
        unsigned i = blockIdx.x - actBlocks;       // 0..1279
        int z = i >> 8;
        int rem = i & 255;
        int by = rem >> 4, bx = rem & 15;
        const float* W = wt.w[z];
        __nv_bfloat16* Th = wt.h[z];
        __nv_bfloat16* Tl = wt.l[z];
        int tx = threadIdx.x & 31, ty = threadIdx.x >> 5;
#pragma unroll
        for (int r = 0; r < 4; r++)
            tile[ty + r * 8][tx] = W[(size_t)(by * 32 + ty + r * 8) * DM + bx * 32 + tx];
        __syncthreads();
#pragma unroll
        for (int r = 0; r < 4; r++) {
            float x = tile[tx][ty + r * 8];
            float h, l;
            split1(x, h, l);
            size_t o = (size_t)(bx * 32 + ty + r * 8) * DM + by * 32 + tx;
            Th[o] = __float2bfloat16_rn(h);
            Tl[o] = __float2bfloat16_rn(l);
        }
    }
}

// ================= mma.sync bf16 3-pass GEMM ===============================
#define GSTRIDE 20
#define AW      (64*GSTRIDE)
#define BW      (128*GSTRIDE)
#define STW     (2*AW + 2*BW)
#define NSTAGE  3
#define GSMEM_BYTES (NSTAGE*STW*4)

struct GemmEnt {
    const __nv_bfloat16 *Ah, *Al, *Bth, *Btl;
    float* C;
    int M, rowsPer, mode;
};
struct Gemm4 { GemmEnt e[4]; };

static __device__ __forceinline__ void store_pair(
    float* C, int mode, int rowsPer, int r, int cn, float x, float y, int M)
{
    if (r >= M) return;
    float2 v = make_float2(x, y);
    if (mode == 0) {
        *(float2*)&C[(size_t)r * DM + cn] = v;
    } else {
        int b = r / rowsPer, rr = r - b * rowsPer;
        int h = cn >> 6, e = cn & 63;
        *(float2*)&C[((size_t)(b * H_ + h) * rowsPer + rr) * E_ + e] = v;
    }
}

static __device__ __forceinline__ void gemm_body(
    const GemmEnt Q, int m0, int n0)
{
    extern __shared__ uint32_t smw[];
    int tid = threadIdx.x, lane = tid & 31, wid = tid >> 5;
    int g = lane >> 2, t = lane & 3;
    int wm = wid & 1, wn = wid >> 1;

    float acc[2][4][4];
#pragma unroll
    for (int i = 0; i < 2; i++)
#pragma unroll
        for (int j = 0; j < 4; j++)
#pragma unroll
            for (int q = 0; q < 4; q++) acc[i][j][q] = 0.f;

    // unified copier: 1536 16B units per chunk (A: 512, B: 1024), 6 per thread
    const __nv_bfloat16* srcs[6];
    uint32_t dsts[6];
#pragma unroll
    for (int j = 0; j < 6; j++) {
        int u = tid + j * 256;
        bool isA = u < 512;
        int v = isA ? u : (u - 512);
        int row = v >> 3;
        int seg = v & 7;
        bool hi = seg < 4;
        int s4 = hi ? seg : (seg - 4);
        int rowC = row;
        if (isA && (m0 + rowC >= Q.M)) {
            rowC = Q.M - 1 - m0;
            if (rowC < 0) rowC = 0;
        }
        const __nv_bfloat16* base;
        if (isA) base = (hi ? Q.Ah : Q.Al) + (size_t)(m0 + rowC) * DM;
        else     base = (hi ? Q.Bth : Q.Btl) + (size_t)(n0 + row) * DM;
        srcs[j] = base + s4 * 8;
        uint32_t regionOff = isA ? (hi ? 0u : (uint32_t)AW)
                                 : (hi ? (uint32_t)(2*AW) : (uint32_t)(2*AW + BW));
        dsts[j] = regionOff + row * GSTRIDE + s4 * 4;
    }
    uint32_t smb = smem_u32(smw);

    auto issue = [&](int ic, int stage) {
#pragma unroll
        for (int j = 0; j < 6; j++)
            cpasync16(smb + (stage * STW + dsts[j]) * 4, srcs[j] + ic * KCH);
    };

    int arow = wm * 32 + (lane & 7) + ((lane >> 3) & 1) * 8;
    int acol = (lane >> 4) * 4;
    int brow = wn * 32 + (lane & 7) + (lane >> 4) * 8;
    int bcol = ((lane >> 3) & 1) * 4;

    issue(0, 0); CP_COMMIT();
    issue(1, 1); CP_COMMIT();

    for (int ic = 0; ic < NCHUNK; ic++) {
        int buf = ic % NSTAGE;
        CP_WAIT1();
        __syncthreads();
        if (ic + 2 < NCHUNK) issue(ic + 2, (ic + 2) % NSTAGE);
        CP_COMMIT();

        uint32_t stage0 = smb + (buf * STW) * 4;
#pragma unroll
        for (int ks = 0; ks < 2; ks++) {
            uint32_t ah[2][4], al[2][4], bh[2][4], bl[2][4];
#pragma unroll
            for (int i = 0; i < 2; i++) {
                uint32_t ao = stage0 + ((arow + i * 16) * GSTRIDE + acol + ks * 8) * 4;
                ldsm4(ah[i], ao);
                ldsm4(al[i], ao + AW * 4);
            }
#pragma unroll
            for (int p = 0; p < 2; p++) {
                uint32_t bo = stage0 + (2 * AW + (brow + p * 16) * GSTRIDE + bcol + ks * 8) * 4;
                ldsm4(bh[p], bo);
                ldsm4(bl[p], bo + BW * 4);
            }
#pragma unroll
            for (int i = 0; i < 2; i++) {
#pragma unroll
                for (int p = 0; p < 2; p++) {
                    mma_bf16(acc[i][2*p],   ah[i], &bh[p][0]);
                    mma_bf16(acc[i][2*p+1], ah[i], &bh[p][2]);
                }
#pragma unroll
                for (int p = 0; p < 2; p++) {
                    mma_bf16(acc[i][2*p],   ah[i], &bl[p][0]);
                    mma_bf16(acc[i][2*p+1], ah[i], &bl[p][2]);
                }
#pragma unroll
                for (int p = 0; p < 2; p++) {
                    mma_bf16(acc[i][2*p],   al[i], &bh[p][0]);
                    mma_bf16(acc[i][2*p+1], al[i], &bh[p][2]);
                }
            }
        }
    }

#pragma unroll
    for (int i = 0; i < 2; i++) {
        int r = m0 + wm * 32 + i * 16 + g;
#pragma unroll
        for (int j = 0; j < 4; j++) {
            int cn = n0 + wn * 32 + j * 8 + t * 2;
            store_pair(Q.C, Q.mode, Q.rowsPer, r,     cn, acc[i][j][0], acc[i][j][1], Q.M);
            store_pair(Q.C, Q.mode, Q.rowsPer, r + 8, cn, acc[i][j][2], acc[i][j][3], Q.M);
        }
    }
}

__global__ __launch_bounds__(256, 2) void mma_gemm_multi(Gemm4 P)
{
    int bx = blockIdx.x;
    int z, xm;
    if (bx == 0) { z = 0; xm = 0; }
    else { z = 1 + ((bx - 1) >> 6); xm = (bx - 1) & 63; }
    gemm_body(P.e[z], xm * 64, blockIdx.y * 128);
}

__global__ __launch_bounds__(256, 2) void mma_gemm_one(GemmEnt Q)
{
    gemm_body(Q, blockIdx.x * 64, blockIdx.y * 128);
}

// ---------------- scores (round-11 body) + fused deterministic mean --------
__global__ __launch_bounds__(256) void scores_kernel()
{
    int bh = blockIdx.x, stile = blockIdx.y;   // grid (16, 8)
    int tid = threadIdx.x;
    int s = stile * 256 + tid;

    __shared__ float csS[G_ * 64];
    __shared__ double sh[256];
    __shared__ int isLast;

    ((float4*)csS)[tid] = ((const float4*)(g_cs + (size_t)bh * G_ * 64))[tid];
    __syncthreads();

    float kkr[64];
    const float4* kp = (const float4*)(g_kk + ((size_t)bh * S_ + s) * 64);
#pragma unroll
    for (int i = 0; i < 16; i++) {
        float4 v = kp[i];
        kkr[i*4] = v.x; kkr[i*4+1] = v.y; kkr[i*4+2] = v.z; kkr[i*4+3] = v.w;
    }

    double local = 0.0;
#pragma unroll
    for (int g = 0; g < G_; g++) {
        float d = 0.f;
#pragma unroll
        for (int e = 0; e < 64; e++) d += csS[g * 64 + e] * kkr[e];
        d *= 0.125f;
        g_scores[((size_t)(bh * G_ + g)) * S_ + s] = d;
        local += (double)d;
    }

    sh[tid] = local;
    __syncthreads();
    for (int o = 128; o; o >>= 1) {
        if (tid < o) sh[tid] += sh[tid + o];
        __syncthreads();
    }
    if (tid == 0) {
        g_partial[stile * G_ + bh] = sh[0];
        __threadfence();
        isLast = (atomicAdd(&g_ctr, 1) == 127);
    }
    __syncthreads();

    if (isLast) {
        __threadfence();
        sh[tid] = (tid < 128) ? g_partial[tid] : 0.0;
        __syncthreads();
        for (int o = 128; o; o >>= 1) {
            if (tid < o) sh[tid] += sh[tid + o];
            __syncthreads();
        }
        if (tid == 0) {
            g_mean = (float)(sh[0] / (double)((size_t)NCHAIN * S_));
            g_ctr = 0;
        }
    }
}

// ---------------- chunk sums (wexp fused) ----------------
__global__ __launch_bounds__(512) void chunk_sums_kernel()
{
    int bh = blockIdx.x, c = blockIdx.y;
    int tid = threadIdx.x;
    int g = tid >> 5, lane = tid & 31;

    __shared__ float kkS[CT * 64], vsS[CT * 64];
    ((float4*)kkS)[tid] = ((const float4*)(g_kk + ((size_t)bh * S_ + c * CT) * 64))[tid];
    ((float4*)vsS)[tid] = ((const float4*)(g_vs + ((size_t)bh * S_ + c * CT) * 64))[tid];

    int chain = bh * G_ + g;
    size_t widx = (size_t)chain * S_ + c * CT + lane;
    float wreg = expf(g_scores[widx] - g_mean);
    g_wexp[widx] = wreg;
    __syncthreads();

    float nw = 0.f, ak0 = 0.f, ak1 = 0.f, av0 = 0.f, av1 = 0.f;
#pragma unroll
    for (int t = 0; t < CT; t++) {
        float w = __shfl_sync(0xffffffffu, wreg, t);
        nw += w;
        ak0 += w * kkS[t * 64 + lane];
        ak1 += w * kkS[t * 64 + lane + 32];
        av0 += w * vsS[t * 64 + lane];
        av1 += w * vsS[t * 64 + lane + 32];
    }
    float* op = g_chunk + ((size_t)chain * CH + c) * REC;
    op[1 + lane]  = ak0;
    op[33 + lane] = ak1;
    op[65 + lane] = av0;
    op[97 + lane] = av1;
    if (lane == 0) op[0] = nw;
}

// ---------------- chunk prefix: bulk smem scan ----------------
#define PF_W4 ((CH*REC)/4)
__global__ __launch_bounds__(160) void chunk_prefix_kernel()
{
    __shared__ float sm[CH * REC];
    int chain = blockIdx.x;
    int tid = threadIdx.x;
    float4* smv = (float4*)sm;
    const float4* src = (const float4*)(g_chunk + (size_t)chain * CH * REC);
    for (int i = tid; i < PF_W4; i += 160) smv[i] = src[i];
    __syncthreads();
    if (tid < REC) {
        float run = 0.f;
#pragma unroll
        for (int c = 0; c < CH; c++) {
            float v = sm[c * REC + tid];
            sm[c * REC + tid] = run;
            run += v;
        }
    }
    __syncthreads();
    float4* dst = (float4*)(g_chunk + (size_t)chain * CH * REC);
    for (int i = tid; i < PF_W4; i += 160) dst[i] = smv[i];
}

// ---------------- attn_scan v3: 4 barriers, direct bf16 output -------------
__global__ __launch_bounds__(512) void attn_scan_kernel()
{
    int bh = blockIdx.x, c = blockIdx.y;
    int tid = threadIdx.x;
    int g = tid >> 5, lane = tid & 31;

    __shared__ float kkS[CT * 64], vsS[CT * 64], qsS[CT * 64];
    __shared__ float Sv0[G_][64];
    __shared__ float Lg[CT][17];
    __shared__ float Nn[CT][17];
    __shared__ float Cc[CT][17];
    __shared__ float Wsm[G_][CT + 1];
    __shared__ float Mm[CT][CT + 1];

    const float* kkBase = g_kk + ((size_t)bh * S_ + c * CT) * E_;
    const float* vsBase = g_vs + ((size_t)bh * S_ + c * CT) * E_;
    const float* qsBase = g_qs + ((size_t)bh * S_ + c * CT) * E_;
    ((float4*)kkS)[tid] = ((const float4*)kkBase)[tid];
    ((float4*)vsS)[tid] = ((const float4*)vsBase)[tid];
    ((float4*)qsS)[tid] = ((const float4*)qsBase)[tid];

    const float* pf = g_chunk + ((size_t)(bh * G_ + g) * CH + c) * REC;
    float nw  = pf[0];
    float skA = pf[1 + lane];
    float skB = pf[33 + lane];
    Sv0[g][lane]      = pf[65 + lane];
    Sv0[g][lane + 32] = pf[97 + lane];
    float wchunk = g_wexp[(size_t)(bh * G_ + g) * S_ + c * CT + lane];
    Wsm[g][lane] = wchunk;
    __syncthreads();

    // phase 1: per-warp Sk scan + logits
#pragma unroll
    for (int t = 0; t < CT; t++) {
        float w = __shfl_sync(0xffffffffu, wchunk, t);
        nw  += w;
        skA += w * kkS[t * 64 + lane];
        skB += w * kkS[t * 64 + lane + 32];
        float d = qsS[t * 64 + lane] * skA + qsS[t * 64 + lane + 32] * skB;
#pragma unroll
        for (int o = 16; o; o >>= 1) d += __shfl_xor_sync(0xffffffffu, d, o);
        if (lane == 0) {
            float nwc = fmaxf(nw, 1e-8f);
            Lg[t][g] = d / nwc;
            Nn[t][g] = nwc;
        }
    }
    __syncthreads();

    // phase 2: softmax over g
    {
        int t2 = 2 * g + (lane >> 4);
        int gg = lane & 15;
        float x = Lg[t2][gg];
        float m = x;
#pragma unroll
        for (int o = 8; o; o >>= 1) m = fmaxf(m, __shfl_xor_sync(0xffffffffu, m, o));
        float e = expf(x - m);
        float ss = e;
#pragma unroll
        for (int o = 8; o; o >>= 1) ss += __shfl_xor_sync(0xffffffffu, ss, o);
        Cc[t2][gg] = (e / ss) / Nn[t2][gg];
    }
    __syncthreads();

    // phase 3a: M[t][tau]
#pragma unroll
    for (int r = 0; r < 2; r++) {
        int idx = tid + r * 512;
        int t = idx >> 5, tau = idx & 31;
        float m = 0.f;
#pragma unroll
        for (int gg = 0; gg < G_; gg++) m += Cc[t][gg] * Wsm[gg][tau];
        Mm[t][tau] = m;
    }
    __syncthreads();

    // phase 3b: out + bf16 split
    {
        int t  = tid >> 4;
        int eg = (tid & 15) * 4;
        float a0 = 0.f, a1 = 0.f, a2 = 0.f, a3 = 0.f;
#pragma unroll
        for (int gg = 0; gg < G_; gg++) {
            float cg = Cc[t][gg];
            float4 sv = *(const float4*)&Sv0[gg][eg];
            a0 += cg * sv.x; a1 += cg * sv.y; a2 += cg * sv.z; a3 += cg * sv.w;
        }
        for (int tau = 0; tau <= t; tau++) {
            float m = Mm[t][tau];
            float4 vv = *(const float4*)&vsS[tau * 64 + eg];
            a0 += m * vv.x; a1 += m * vv.y; a2 += m * vv.z; a3 += m * vv.w;
        }
        float h0,h1,h2,h3,l0,l1,l2,l3;
        split1(a0,h0,l0); split1(a1,h1,l1); split1(a2,h2,l2); split1(a3,h3,l3);
        int b = bh >> 3, h = bh & 7;
        size_t off = ((size_t)b * S_ + c * CT + t) * DM + h * 64 + eg;
        __nv_bfloat16* ahp = (__nv_bfloat16*)g_ah4;
        __nv_bfloat16* alp = (__nv_bfloat16*)g_al4;
        *(uint2*)(ahp + off) = make_uint2(pack2(h0,h1), pack2(h2,h3));
        *(uint2*)(alp + off) = make_uint2(pack2(l0,l1), pack2(l2,l3));
    }
}

// ---------------- launch ---------------------------------------------------
extern "C" void kernel_launch(void* const* d_in, const int* in_sizes, int n_in,
                              void* d_out, int out_size)
{
    const float* q   = (const float*)d_in[0];
    const float* k   = (const float*)d_in[1];
    const float* v   = (const float*)d_in[2];
    const float* ctx = (const float*)d_in[3];

    typedef __nv_bfloat16 bf;
    static float *p_qs = nullptr, *p_kk, *p_vs, *p_cs;
    static bf *qh,*ql,*kh,*kl,*vh,*vl,*ch,*cl;
    static bf *wqh,*wql,*wkh,*wkl,*wvh,*wvl,*woh,*wol,*wch,*wcl;
    static bf *ah,*al;
    if (!p_qs) {
        cudaGetSymbolAddress((void**)&p_qs,   g_qs);
        cudaGetSymbolAddress((void**)&p_kk,   g_kk);
        cudaGetSymbolAddress((void**)&p_vs,   g_vs);
        cudaGetSymbolAddress((void**)&p_cs,   g_cs);
        cudaGetSymbolAddress((void**)&qh, g_qh4);  cudaGetSymbolAddress((void**)&ql, g_ql4);
        cudaGetSymbolAddress((void**)&kh, g_kh4);  cudaGetSymbolAddress((void**)&kl, g_kl4);
        cudaGetSymbolAddress((void**)&vh, g_vh4);  cudaGetSymbolAddress((void**)&vl, g_vl4);
        cudaGetSymbolAddress((void**)&ch, g_ch4);  cudaGetSymbolAddress((void**)&cl, g_cl4);
        cudaGetSymbolAddress((void**)&wqh, g_wqh4); cudaGetSymbolAddress((void**)&wql, g_wql4);
        cudaGetSymbolAddress((void**)&wkh, g_wkh4); cudaGetSymbolAddress((void**)&wkl, g_wkl4);
        cudaGetSymbolAddress((void**)&wvh, g_wvh4); cudaGetSymbolAddress((void**)&wvl, g_wvl4);
        cudaGetSymbolAddress((void**)&woh, g_woh4); cudaGetSymbolAddress((void**)&wol, g_wol4);
        cudaGetSymbolAddress((void**)&wch, g_wch4); cudaGetSymbolAddress((void**)&wcl, g_wcl4);
        cudaGetSymbolAddress((void**)&ah, g_ah4);   cudaGetSymbolAddress((void**)&al, g_al4);
        cudaFuncSetAttribute(mma_gemm_multi, cudaFuncAttributeMaxDynamicSharedMemorySize, GSMEM_BYTES);
        cudaFuncSetAttribute(mma_gemm_one,   cudaFuncAttributeMaxDynamicSharedMemorySize, GSMEM_BYTES);
    }

    const unsigned N_BIG = (B_*S_*DM)/4;
    const unsigned N_CTX = (B_*G_*DM)/4;

    Conv4 c4;
    c4.seg[0] = { q,   qh, ql, N_BIG };
    c4.seg[1] = { k,   kh, kl, N_BIG };
    c4.seg[2] = { v,   vh, vl, N_BIG };
    c4.seg[3] = { ctx, ch, cl, N_CTX };
    unsigned total4 = 3 * N_BIG + N_CTX;
    unsigned actBlocks = (total4 + 255) / 256;

    WT5 wt;
    wt.w[0] = (const float*)d_in[4]; wt.h[0] = wqh; wt.l[0] = wql;
    wt.w[1] = (const float*)d_in[5]; wt.h[1] = wkh; wt.l[1] = wkl;
    wt.w[2] = (const float*)d_in[6]; wt.h[2] = wvh; wt.l[2] = wvl;
    wt.w[3] = (const float*)d_in[7]; wt.h[3] = woh; wt.l[3] = wol;
    wt.w[4] = (const float*)d_in[8]; wt.h[4] = wch; wt.l[4] = wcl;

    convert_all<<<actBlocks + 1280, 256>>>(c4, total4, actBlocks, wt);

    Gemm4 P;
    P.e[0] = { ch, cl, wch, wcl, p_cs, B_ * G_, G_, 1 };
    P.e[1] = { qh, ql, wqh, wql, p_qs, B_ * S_, S_, 1 };
    P.e[2] = { kh, kl, wkh, wkl, p_kk, B_ * S_, S_, 1 };
    P.e[3] = { vh, vl, wvh, wvl, p_vs, B_ * S_, S_, 1 };
    mma_gemm_multi<<<dim3(193, 4), 256, GSMEM_BYTES>>>(P);

    scores_kernel<<<dim3(G_, 8), 256>>>();
    chunk_sums_kernel<<<dim3(G_, CH), 512>>>();
    chunk_prefix_kernel<<<NCHAIN, 160>>>();
    attn_scan_kernel<<<dim3(B_ * H_, CH), 512>>>();

    GemmEnt Qo = { ah, al, woh, wol, (float*)d_out, B_ * S_, S_, 0 };
    mma_gemm_one<<<dim3(64, 4), 256, GSMEM_BYTES>>>(Qo);
}

// round 16
// speedup vs baseline: 1.0011x; 1.0011x over previous
#include <cuda_runtime.h>
#include <cuda_bf16.h>
#include <cstdint>

#define B_   2
#define H_   8
#define G_   16
#define S_   2048
#define E_   64
#define DM   512
#define CT   32
#define CH   (S_/CT)
#define NCHAIN (B_*H_*G_)
#define REC  132
#define KCH  32
#define NCHUNK (DM/KCH)

// ---------------- fp32 scratch ----------------
__device__ float  g_qs[B_*H_*S_*E_];
__device__ float  g_kk[B_*H_*S_*E_];
__device__ float  g_vs[B_*H_*S_*E_];
__device__ float  g_cs[B_*H_*G_*E_];
__device__ float  g_scores[NCHAIN*S_];
__device__ float  g_wexp[NCHAIN*S_];
__device__ float  g_chunk[NCHAIN*CH*REC];
__device__ double g_partial[128];
__device__ float  g_mean;

// ---------------- bf16 hi/lo buffers ----------------
__device__ uint4 g_qh4[262144], g_ql4[262144];
__device__ uint4 g_kh4[262144], g_kl4[262144];
__device__ uint4 g_vh4[262144], g_vl4[262144];
__device__ uint4 g_ch4[2048],   g_cl4[2048];
__device__ uint4 g_wqh4[32768], g_wql4[32768];
__device__ uint4 g_wkh4[32768], g_wkl4[32768];
__device__ uint4 g_wvh4[32768], g_wvl4[32768];
__device__ uint4 g_woh4[32768], g_wol4[32768];
__device__ uint4 g_wch4[32768], g_wcl4[32768];
__device__ uint4 g_ah4[262144], g_al4[262144];

// ---------------- helpers ----------------
static __device__ __forceinline__ uint32_t pack2(float a, float b) {
    __nv_bfloat162 t = __floats2bfloat162_rn(a, b);
    return *reinterpret_cast<uint32_t*>(&t);
}
static __device__ __forceinline__ void split1(float x, float& hi, float& lo) {
    __nv_bfloat16 h = __float2bfloat16_rn(x);
    hi = __bfloat162float(h);
    lo = x - hi;
}
static __device__ __forceinline__ void mma_bf16(float* c, const uint32_t* a, const uint32_t* b) {
    asm volatile(
        "mma.sync.aligned.m16n8k16.row.col.f32.bf16.bf16.f32 "
        "{%0,%1,%2,%3}, {%4,%5,%6,%7}, {%8,%9}, {%0,%1,%2,%3};"
        : "+f"(c[0]), "+f"(c[1]), "+f"(c[2]), "+f"(c[3])
        : "r"(a[0]), "r"(a[1]), "r"(a[2]), "r"(a[3]), "r"(b[0]), "r"(b[1]));
}
static __device__ __forceinline__ uint32_t smem_u32(const void* p) {
    uint32_t a;
    asm("{ .reg .u64 t; cvta.to.shared.u64 t, %1; cvt.u32.u64 %0, t; }" : "=r"(a) : "l"(p));
    return a;
}
static __device__ __forceinline__ void cpasync16(uint32_t dst, const void* src) {
    asm volatile("cp.async.cg.shared.global [%0], [%1], 16;" :: "r"(dst), "l"(src));
}
#define CP_COMMIT() asm volatile("cp.async.commit_group;" ::: "memory")
#define CP_WAIT1()  asm volatile("cp.async.wait_group 1;" ::: "memory")
static __device__ __forceinline__ void ldsm4(uint32_t* r, uint32_t addr) {
    asm volatile("ldmatrix.sync.aligned.m8n8.x4.shared.b16 {%0,%1,%2,%3}, [%4];"
        : "=r"(r[0]), "=r"(r[1]), "=r"(r[2]), "=r"(r[3]) : "r"(addr));
}

// ---------------- unified conversion (activations + transposed weights) ----
struct ConvSeg { const float* s; __nv_bfloat16* h; __nv_bfloat16* l; unsigned n4; };
struct Conv4 { ConvSeg seg[4]; };
struct WT5 { const float* w[5]; __nv_bfloat16* h[5]; __nv_bfloat16* l[5]; };

__global__ __launch_bounds__(256) void convert_all(
    Conv4 c, unsigned total4, unsigned actBlocks, WT5 wt)
{
    __shared__ float tile[32][33];
    if (blockIdx.x < actBlocks) {
        unsigned i = blockIdx.x * 256u + threadIdx.x;
        if (i >= total4) return;
        unsigned off = i;
#pragma unroll
        for (int s = 0; s < 4; s++) {
            unsigned n4 = c.seg[s].n4;
            if (off < n4) {
                float4 v = ((const float4*)c.seg[s].s)[off];
                float h0,h1,h2,h3,l0,l1,l2,l3;
                split1(v.x,h0,l0); split1(v.y,h1,l1); split1(v.z,h2,l2); split1(v.w,h3,l3);
                ((uint2*)c.seg[s].h)[off] = make_uint2(pack2(h0,h1), pack2(h2,h3));
                ((uint2*)c.seg[s].l)[off] = make_uint2(pack2(l0,l1), pack2(l2,l3));
                return;
            }
            off -= n4;
        }
    } else {
        unsigned i = blockIdx.x - actBlocks;       // 0..1279
        int z = i >> 8;
        int rem = i & 255;
        int by = rem >> 4, bx = rem & 15;
        const float* W = wt.w[z];
        __nv_bfloat16* Th = wt.h[z];
        __nv_bfloat16* Tl = wt.l[z];
        int tx = threadIdx.x & 31, ty = threadIdx.x >> 5;
#pragma unroll
        for (int r = 0; r < 4; r++)
            tile[ty + r * 8][tx] = W[(size_t)(by * 32 + ty + r * 8) * DM + bx * 32 + tx];
        __syncthreads();
#pragma unroll
        for (int r = 0; r < 4; r++) {
            float x = tile[tx][ty + r * 8];
            float h, l;
            split1(x, h, l);
            size_t o = (size_t)(bx * 32 + ty + r * 8) * DM + by * 32 + tx;
            Th[o] = __float2bfloat16_rn(h);
            Tl[o] = __float2bfloat16_rn(l);
        }
    }
}

// ================= mma.sync bf16 3-pass GEMM (round-12 body) ===============
#define GSTRIDE 20
#define AW      (64*GSTRIDE)
#define BW      (128*GSTRIDE)
#define STW     (2*AW + 2*BW)
#define NSTAGE  3
#define GSMEM_BYTES (NSTAGE*STW*4)

struct GemmEnt {
    const __nv_bfloat16 *Ah, *Al, *Bth, *Btl;
    float* C;
    int M, rowsPer, mode;
};
struct Gemm4 { GemmEnt e[4]; };

static __device__ __forceinline__ void store_pair(
    float* C, int mode, int rowsPer, int r, int cn, float x, float y, int M)
{
    if (r >= M) return;
    float2 v = make_float2(x, y);
    if (mode == 0) {
        *(float2*)&C[(size_t)r * DM + cn] = v;
    } else {
        int b = r / rowsPer, rr = r - b * rowsPer;
        int h = cn >> 6, e = cn & 63;
        *(float2*)&C[((size_t)(b * H_ + h) * rowsPer + rr) * E_ + e] = v;
    }
}

static __device__ __forceinline__ void gemm_body(
    const GemmEnt Q, int m0, int n0)
{
    extern __shared__ uint32_t smw[];
    int tid = threadIdx.x, lane = tid & 31, wid = tid >> 5;
    int g = lane >> 2, t = lane & 3;
    int wm = wid & 1, wn = wid >> 1;

    float acc[2][4][4];
#pragma unroll
    for (int i = 0; i < 2; i++)
#pragma unroll
        for (int j = 0; j < 4; j++)
#pragma unroll
            for (int q = 0; q < 4; q++) acc[i][j][q] = 0.f;

    bool isA = tid < 128;
    int u = isA ? tid : (tid - 128);
    const __nv_bfloat16* segH[2];
    const __nv_bfloat16* segL[2];
    uint32_t segD[2];
    uint32_t loOff;
    int nseg;
    if (isA) {
        int row = u >> 1, half = u & 1;
        int rowC = row;
        if (m0 + rowC >= Q.M) { rowC = Q.M - 1 - m0; if (rowC < 0) rowC = 0; }
        segH[0] = Q.Ah + (size_t)(m0 + rowC) * DM + half * 16;
        segL[0] = Q.Al + (size_t)(m0 + rowC) * DM + half * 16;
        segD[0] = row * GSTRIDE + half * 8;
        loOff = AW; nseg = 1;
        segH[1] = segH[0]; segL[1] = segL[0]; segD[1] = segD[0];
    } else {
        loOff = BW; nseg = 2;
#pragma unroll
        for (int s = 0; s < 2; s++) {
            int unit = u + s * 128;
            int row = unit >> 1, half = unit & 1;
            segH[s] = Q.Bth + (size_t)(n0 + row) * DM + half * 16;
            segL[s] = Q.Btl + (size_t)(n0 + row) * DM + half * 16;
            segD[s] = 2 * AW + row * GSTRIDE + half * 8;
        }
    }
    uint32_t smb = smem_u32(smw);

    auto issue = [&](int ic, int stage) {
#pragma unroll
        for (int s = 0; s < 2; s++) {
            if (s >= nseg) break;
            const __nv_bfloat16* ph = segH[s] + ic * KCH;
            const __nv_bfloat16* pl = segL[s] + ic * KCH;
            uint32_t w = stage * STW + segD[s];
            cpasync16(smb + w * 4, ph);
            cpasync16(smb + (w + 4) * 4, ph + 8);
            cpasync16(smb + (w + loOff) * 4, pl);
            cpasync16(smb + (w + loOff + 4) * 4, pl + 8);
        }
    };

    int arow = wm * 32 + (lane & 7) + ((lane >> 3) & 1) * 8;
    int acol = (lane >> 4) * 4;
    int brow = wn * 32 + (lane & 7) + (lane >> 4) * 8;
    int bcol = ((lane >> 3) & 1) * 4;

    issue(0, 0); CP_COMMIT();
    issue(1, 1); CP_COMMIT();

    for (int ic = 0; ic < NCHUNK; ic++) {
        int buf = ic % NSTAGE;
        CP_WAIT1();
        __syncthreads();
        if (ic + 2 < NCHUNK) issue(ic + 2, (ic + 2) % NSTAGE);
        CP_COMMIT();

        uint32_t stage0 = smb + (buf * STW) * 4;
#pragma unroll
        for (int ks = 0; ks < 2; ks++) {
            uint32_t ah[2][4], al[2][4], bh[2][4], bl[2][4];
#pragma unroll
            for (int i = 0; i < 2; i++) {
                uint32_t ao = stage0 + ((arow + i * 16) * GSTRIDE + acol + ks * 8) * 4;
                ldsm4(ah[i], ao);
                ldsm4(al[i], ao + AW * 4);
            }
#pragma unroll
            for (int p = 0; p < 2; p++) {
                uint32_t bo = stage0 + (2 * AW + (brow + p * 16) * GSTRIDE + bcol + ks * 8) * 4;
                ldsm4(bh[p], bo);
                ldsm4(bl[p], bo + BW * 4);
            }
#pragma unroll
            for (int i = 0; i < 2; i++) {
#pragma unroll
                for (int p = 0; p < 2; p++) {
                    mma_bf16(acc[i][2*p],   ah[i], &bh[p][0]);
                    mma_bf16(acc[i][2*p+1], ah[i], &bh[p][2]);
                }
#pragma unroll
                for (int p = 0; p < 2; p++) {
                    mma_bf16(acc[i][2*p],   ah[i], &bl[p][0]);
                    mma_bf16(acc[i][2*p+1], ah[i], &bl[p][2]);
                }
#pragma unroll
                for (int p = 0; p < 2; p++) {
                    mma_bf16(acc[i][2*p],   al[i], &bh[p][0]);
                    mma_bf16(acc[i][2*p+1], al[i], &bh[p][2]);
                }
            }
        }
    }

#pragma unroll
    for (int i = 0; i < 2; i++) {
        int r = m0 + wm * 32 + i * 16 + g;
#pragma unroll
        for (int j = 0; j < 4; j++) {
            int cn = n0 + wn * 32 + j * 8 + t * 2;
            store_pair(Q.C, Q.mode, Q.rowsPer, r,     cn, acc[i][j][0], acc[i][j][1], Q.M);
            store_pair(Q.C, Q.mode, Q.rowsPer, r + 8, cn, acc[i][j][2], acc[i][j][3], Q.M);
        }
    }
}

__global__ __launch_bounds__(256, 2) void mma_gemm_multi(Gemm4 P)
{
    int bx = blockIdx.x;
    int z, xm;
    if (bx == 0) { z = 0; xm = 0; }
    else { z = 1 + ((bx - 1) >> 6); xm = (bx - 1) & 63; }
    gemm_body(P.e[z], xm * 64, blockIdx.y * 128);
}

__global__ __launch_bounds__(256, 2) void mma_gemm_one(GemmEnt Q)
{
    gemm_body(Q, blockIdx.x * 64, blockIdx.y * 128);
}

// ---------------- scores (round-11 variant: grid (16,8), 256 thr) ----------
__global__ __launch_bounds__(256) void scores_kernel()
{
    int bh = blockIdx.x, stile = blockIdx.y;
    int tid = threadIdx.x;
    int s = stile * 256 + tid;

    __shared__ float csS[G_ * 64];
    ((float4*)csS)[tid] = ((const float4*)(g_cs + (size_t)bh * G_ * 64))[tid];
    __syncthreads();

    float kkr[64];
    const float4* kp = (const float4*)(g_kk + ((size_t)bh * S_ + s) * 64);
#pragma unroll
    for (int i = 0; i < 16; i++) {
        float4 v = kp[i];
        kkr[i*4] = v.x; kkr[i*4+1] = v.y; kkr[i*4+2] = v.z; kkr[i*4+3] = v.w;
    }

    double local = 0.0;
#pragma unroll
    for (int g = 0; g < G_; g++) {
        float d = 0.f;
#pragma unroll
        for (int e = 0; e < 64; e++) d += csS[g * 64 + e] * kkr[e];
        d *= 0.125f;
        g_scores[((size_t)(bh * G_ + g)) * S_ + s] = d;
        local += (double)d;
    }

    __shared__ double sh[256];
    sh[tid] = local;
    __syncthreads();
    for (int o = 128; o; o >>= 1) {
        if (tid < o) sh[tid] += sh[tid + o];
        __syncthreads();
    }
    if (tid == 0) g_partial[stile * G_ + bh] = sh[0];
}

__global__ __launch_bounds__(128) void mean_kernel()
{
    __shared__ double sh[128];
    int t = threadIdx.x;
    sh[t] = g_partial[t];
    __syncthreads();
    for (int o = 64; o; o >>= 1) {
        if (t < o) sh[t] += sh[t + o];
        __syncthreads();
    }
    if (t == 0) g_mean = (float)(sh[0] / (double)((size_t)NCHAIN * S_));
}

__global__ __launch_bounds__(256) void wexp_kernel()
{
    int i = blockIdx.x * 256 + threadIdx.x;
    g_wexp[i] = expf(g_scores[i] - g_mean);
}

// ---------------- chunk sums (round-12) ----------------
__global__ __launch_bounds__(512) void chunk_sums_kernel()
{
    int bh = blockIdx.x, c = blockIdx.y;
    int tid = threadIdx.x;
    int g = tid >> 5, lane = tid & 31;

    __shared__ float kkS[CT * 64], vsS[CT * 64];
    ((float4*)kkS)[tid] = ((const float4*)(g_kk + ((size_t)bh * S_ + c * CT) * 64))[tid];
    ((float4*)vsS)[tid] = ((const float4*)(g_vs + ((size_t)bh * S_ + c * CT) * 64))[tid];

    int chain = bh * G_ + g;
    float wreg = g_wexp[(size_t)chain * S_ + c * CT + lane];
    __syncthreads();

    float nw = 0.f, ak0 = 0.f, ak1 = 0.f, av0 = 0.f, av1 = 0.f;
#pragma unroll
    for (int t = 0; t < CT; t++) {
        float w = __shfl_sync(0xffffffffu, wreg, t);
        nw += w;
        ak0 += w * kkS[t * 64 + lane];
        ak1 += w * kkS[t * 64 + lane + 32];
        av0 += w * vsS[t * 64 + lane];
        av1 += w * vsS[t * 64 + lane + 32];
    }
    float* op = g_chunk + ((size_t)chain * CH + c) * REC;
    op[1 + lane]  = ak0;
    op[33 + lane] = ak1;
    op[65 + lane] = av0;
    op[97 + lane] = av1;
    if (lane == 0) op[0] = nw;
}

// ---------------- chunk prefix (round-12 serial version) -------------------
__global__ __launch_bounds__(160) void chunk_prefix_kernel()
{
    int chain = blockIdx.x;
    int t = threadIdx.x;
    if (t >= 129) return;
    float run = 0.f;
    for (int c = 0; c < CH; c++) {
        size_t idx = ((size_t)chain * CH + c) * REC + t;
        float v = g_chunk[idx];
        g_chunk[idx] = run;
        run += v;
    }
}

// ---------------- attn_scan v3 (round-12): 4 barriers, bf16 out ------------
__global__ __launch_bounds__(512) void attn_scan_kernel()
{
    int bh = blockIdx.x, c = blockIdx.y;
    int tid = threadIdx.x;
    int g = tid >> 5, lane = tid & 31;

    __shared__ float kkS[CT * 64], vsS[CT * 64], qsS[CT * 64];
    __shared__ float Sv0[G_][64];
    __shared__ float Lg[CT][17];
    __shared__ float Nn[CT][17];
    __shared__ float Cc[CT][17];
    __shared__ float Wsm[G_][CT + 1];
    __shared__ float Mm[CT][CT + 1];

    const float* kkBase = g_kk + ((size_t)bh * S_ + c * CT) * E_;
    const float* vsBase = g_vs + ((size_t)bh * S_ + c * CT) * E_;
    const float* qsBase = g_qs + ((size_t)bh * S_ + c * CT) * E_;
    ((float4*)kkS)[tid] = ((const float4*)kkBase)[tid];
    ((float4*)vsS)[tid] = ((const float4*)vsBase)[tid];
    ((float4*)qsS)[tid] = ((const float4*)qsBase)[tid];

    const float* pf = g_chunk + ((size_t)(bh * G_ + g) * CH + c) * REC;
    float nw  = pf[0];
    float skA = pf[1 + lane];
    float skB = pf[33 + lane];
    Sv0[g][lane]      = pf[65 + lane];
    Sv0[g][lane + 32] = pf[97 + lane];
    float wchunk = g_wexp[(size_t)(bh * G_ + g) * S_ + c * CT + lane];
    Wsm[g][lane] = wchunk;
    __syncthreads();

    // phase 1: per-warp Sk scan + logits
#pragma unroll
    for (int t = 0; t < CT; t++) {
        float w = __shfl_sync(0xffffffffu, wchunk, t);
        nw  += w;
        skA += w * kkS[t * 64 + lane];
        skB += w * kkS[t * 64 + lane + 32];
        float d = qsS[t * 64 + lane] * skA + qsS[t * 64 + lane + 32] * skB;
#pragma unroll
        for (int o = 16; o; o >>= 1) d += __shfl_xor_sync(0xffffffffu, d, o);
        if (lane == 0) {
            float nwc = fmaxf(nw, 1e-8f);
            Lg[t][g] = d / nwc;
            Nn[t][g] = nwc;
        }
    }
    __syncthreads();

    // phase 2: softmax over g
    {
        int t2 = 2 * g + (lane >> 4);
        int gg = lane & 15;
        float x = Lg[t2][gg];
        float m = x;
#pragma unroll
        for (int o = 8; o; o >>= 1) m = fmaxf(m, __shfl_xor_sync(0xffffffffu, m, o));
        float e = expf(x - m);
        float ss = e;
#pragma unroll
        for (int o = 8; o; o >>= 1) ss += __shfl_xor_sync(0xffffffffu, ss, o);
        Cc[t2][gg] = (e / ss) / Nn[t2][gg];
    }
    __syncthreads();

    // phase 3a: M[t][tau]
#pragma unroll
    for (int r = 0; r < 2; r++) {
        int idx = tid + r * 512;
        int t = idx >> 5, tau = idx & 31;
        float m = 0.f;
#pragma unroll
        for (int gg = 0; gg < G_; gg++) m += Cc[t][gg] * Wsm[gg][tau];
        Mm[t][tau] = m;
    }
    __syncthreads();

    // phase 3b: out + bf16 split
    {
        int t  = tid >> 4;
        int eg = (tid & 15) * 4;
        float a0 = 0.f, a1 = 0.f, a2 = 0.f, a3 = 0.f;
#pragma unroll
        for (int gg = 0; gg < G_; gg++) {
            float cg = Cc[t][gg];
            float4 sv = *(const float4*)&Sv0[gg][eg];
            a0 += cg * sv.x; a1 += cg * sv.y; a2 += cg * sv.z; a3 += cg * sv.w;
        }
        for (int tau = 0; tau <= t; tau++) {
            float m = Mm[t][tau];
            float4 vv = *(const float4*)&vsS[tau * 64 + eg];
            a0 += m * vv.x; a1 += m * vv.y; a2 += m * vv.z; a3 += m * vv.w;
        }
        float h0,h1,h2,h3,l0,l1,l2,l3;
        split1(a0,h0,l0); split1(a1,h1,l1); split1(a2,h2,l2); split1(a3,h3,l3);
        int b = bh >> 3, h = bh & 7;
        size_t off = ((size_t)b * S_ + c * CT + t) * DM + h * 64 + eg;
        __nv_bfloat16* ahp = (__nv_bfloat16*)g_ah4;
        __nv_bfloat16* alp = (__nv_bfloat16*)g_al4;
        *(uint2*)(ahp + off) = make_uint2(pack2(h0,h1), pack2(h2,h3));
        *(uint2*)(alp + off) = make_uint2(pack2(l0,l1), pack2(l2,l3));
    }
}

// ---------------- launch ---------------------------------------------------
extern "C" void kernel_launch(void* const* d_in, const int* in_sizes, int n_in,
                              void* d_out, int out_size)
{
    const float* q   = (const float*)d_in[0];
    const float* k   = (const float*)d_in[1];
    const float* v   = (const float*)d_in[2];
    const float* ctx = (const float*)d_in[3];

    typedef __nv_bfloat16 bf;
    static float *p_qs = nullptr, *p_kk, *p_vs, *p_cs;
    static bf *qh,*ql,*kh,*kl,*vh,*vl,*ch,*cl;
    static bf *wqh,*wql,*wkh,*wkl,*wvh,*wvl,*woh,*wol,*wch,*wcl;
    static bf *ah,*al;
    if (!p_qs) {
        cudaGetSymbolAddress((void**)&p_qs,   g_qs);
        cudaGetSymbolAddress((void**)&p_kk,   g_kk);
        cudaGetSymbolAddress((void**)&p_vs,   g_vs);
        cudaGetSymbolAddress((void**)&p_cs,   g_cs);
        cudaGetSymbolAddress((void**)&qh, g_qh4);  cudaGetSymbolAddress((void**)&ql, g_ql4);
        cudaGetSymbolAddress((void**)&kh, g_kh4);  cudaGetSymbolAddress((void**)&kl, g_kl4);
        cudaGetSymbolAddress((void**)&vh, g_vh4);  cudaGetSymbolAddress((void**)&vl, g_vl4);
        cudaGetSymbolAddress((void**)&ch, g_ch4);  cudaGetSymbolAddress((void**)&cl, g_cl4);
        cudaGetSymbolAddress((void**)&wqh, g_wqh4); cudaGetSymbolAddress((void**)&wql, g_wql4);
        cudaGetSymbolAddress((void**)&wkh, g_wkh4); cudaGetSymbolAddress((void**)&wkl, g_wkl4);
        cudaGetSymbolAddress((void**)&wvh, g_wvh4); cudaGetSymbolAddress((void**)&wvl, g_wvl4);
        cudaGetSymbolAddress((void**)&woh, g_woh4); cudaGetSymbolAddress((void**)&wol, g_wol4);
        cudaGetSymbolAddress((void**)&wch, g_wch4); cudaGetSymbolAddress((void**)&wcl, g_wcl4);
        cudaGetSymbolAddress((void**)&ah, g_ah4);   cudaGetSymbolAddress((void**)&al, g_al4);
        cudaFuncSetAttribute(mma_gemm_multi, cudaFuncAttributeMaxDynamicSharedMemorySize, GSMEM_BYTES);
        cudaFuncSetAttribute(mma_gemm_one,   cudaFuncAttributeMaxDynamicSharedMemorySize, GSMEM_BYTES);
    }

    const unsigned N_BIG = (B_*S_*DM)/4;
    const unsigned N_CTX = (B_*G_*DM)/4;

    Conv4 c4;
    c4.seg[0] = { q,   qh, ql, N_BIG };
    c4.seg[1] = { k,   kh, kl, N_BIG };
    c4.seg[2] = { v,   vh, vl, N_BIG };
    c4.seg[3] = { ctx, ch, cl, N_CTX };
    unsigned total4 = 3 * N_BIG + N_CTX;
    unsigned actBlocks = (total4 + 255) / 256;

    WT5 wt;
    wt.w[0] = (const float*)d_in[4]; wt.h[0] = wqh; wt.l[0] = wql;
    wt.w[1] = (const float*)d_in[5]; wt.h[1] = wkh; wt.l[1] = wkl;
    wt.w[2] = (const float*)d_in[6]; wt.h[2] = wvh; wt.l[2] = wvl;
    wt.w[3] = (const float*)d_in[7]; wt.h[3] = woh; wt.l[3] = wol;
    wt.w[4] = (const float*)d_in[8]; wt.h[4] = wch; wt.l[4] = wcl;

    convert_all<<<actBlocks + 1280, 256>>>(c4, total4, actBlocks, wt);

    Gemm4 P;
    P.e[0] = { ch, cl, wch, wcl, p_cs, B_ * G_, G_, 1 };
    P.e[1] = { qh, ql, wqh, wql, p_qs, B_ * S_, S_, 1 };
    P.e[2] = { kh, kl, wkh, wkl, p_kk, B_ * S_, S_, 1 };
    P.e[3] = { vh, vl, wvh, wvl, p_vs, B_ * S_, S_, 1 };
    mma_gemm_multi<<<dim3(193, 4), 256, GSMEM_BYTES>>>(P);

    scores_kernel<<<dim3(G_, 8), 256>>>();
    mean_kernel<<<1, 128>>>();
    wexp_kernel<<<(NCHAIN * S_) / 256, 256>>>();
    chunk_sums_kernel<<<dim3(G_, CH), 512>>>();
    chunk_prefix_kernel<<<NCHAIN, 160>>>();
    attn_scan_kernel<<<dim3(B_ * H_, CH), 512>>>();

    GemmEnt Qo = { ah, al, woh, wol, (float*)d_out, B_ * S_, S_, 0 };
    mma_gemm_one<<<dim3(64, 4), 256, GSMEM_BYTES>>>(Qo);
}

// round 17
// speedup vs baseline: 1.1044x; 1.1032x over previous
#include <cuda_runtime.h>
#include <cuda_bf16.h>
#include <cstdint>

#define B_   2
#define H_   8
#define G_   16
#define S_   2048
#define E_   64
#define DM   512
#define CT   32
#define CH   (S_/CT)
#define NCHAIN (B_*H_*G_)
#define REC  132
#define KCH  32
#define NCHUNK (DM/KCH)

// ---------------- fp32 scratch ----------------
__device__ float  g_qs[B_*H_*S_*E_];
__device__ float  g_kk[B_*H_*S_*E_];
__device__ float  g_vs[B_*H_*S_*E_];
__device__ float  g_cs[B_*H_*G_*E_];
__device__ float  g_scores[NCHAIN*S_];
__device__ float  g_wexp[NCHAIN*S_];
__device__ float  g_chunk[NCHAIN*CH*REC];
__device__ double g_partial[256];
__device__ float  g_mean;
__device__ int    g_ctr;

// ---------------- bf16 hi/lo buffers ----------------
__device__ uint4 g_qh4[262144], g_ql4[262144];
__device__ uint4 g_kh4[262144], g_kl4[262144];
__device__ uint4 g_vh4[262144], g_vl4[262144];
__device__ uint4 g_ch4[2048],   g_cl4[2048];
__device__ uint4 g_wqh4[32768], g_wql4[32768];
__device__ uint4 g_wkh4[32768], g_wkl4[32768];
__device__ uint4 g_wvh4[32768], g_wvl4[32768];
__device__ uint4 g_woh4[32768], g_wol4[32768];
__device__ uint4 g_wch4[32768], g_wcl4[32768];
__device__ uint4 g_ah4[262144], g_al4[262144];

// ---------------- helpers ----------------
static __device__ __forceinline__ uint32_t pack2(float a, float b) {
    __nv_bfloat162 t = __floats2bfloat162_rn(a, b);
    return *reinterpret_cast<uint32_t*>(&t);
}
static __device__ __forceinline__ void split1(float x, float& hi, float& lo) {
    __nv_bfloat16 h = __float2bfloat16_rn(x);
    hi = __bfloat162float(h);
    lo = x - hi;
}
static __device__ __forceinline__ void mma_bf16(float* c, const uint32_t* a, const uint32_t* b) {
    asm volatile(
        "mma.sync.aligned.m16n8k16.row.col.f32.bf16.bf16.f32 "
        "{%0,%1,%2,%3}, {%4,%5,%6,%7}, {%8,%9}, {%0,%1,%2,%3};"
        : "+f"(c[0]), "+f"(c[1]), "+f"(c[2]), "+f"(c[3])
        : "r"(a[0]), "r"(a[1]), "r"(a[2]), "r"(a[3]), "r"(b[0]), "r"(b[1]));
}
static __device__ __forceinline__ uint32_t smem_u32(const void* p) {
    uint32_t a;
    asm("{ .reg .u64 t; cvta.to.shared.u64 t, %1; cvt.u32.u64 %0, t; }" : "=r"(a) : "l"(p));
    return a;
}
static __device__ __forceinline__ void cpasync16(uint32_t dst, const void* src) {
    asm volatile("cp.async.cg.shared.global [%0], [%1], 16;" :: "r"(dst), "l"(src));
}
#define CP_COMMIT() asm volatile("cp.async.commit_group;" ::: "memory")
#define CP_WAIT1()  asm volatile("cp.async.wait_group 1;" ::: "memory")
static __device__ __forceinline__ void ldsm4(uint32_t* r, uint32_t addr) {
    asm volatile("ldmatrix.sync.aligned.m8n8.x4.shared.b16 {%0,%1,%2,%3}, [%4];"
        : "=r"(r[0]), "=r"(r[1]), "=r"(r[2]), "=r"(r[3]) : "r"(addr));
}

// ---------------- activation hi/lo split (round-12) ------------------------
struct ConvSeg { const float* s; __nv_bfloat16* h; __nv_bfloat16* l; unsigned n4; };
struct Conv4 { ConvSeg seg[4]; };

__global__ __launch_bounds__(256) void convert_act(Conv4 c, unsigned total4)
{
    unsigned i = blockIdx.x * 256u + threadIdx.x;
    if (i >= total4) return;
    unsigned off = i;
#pragma unroll
    for (int s = 0; s < 4; s++) {
        unsigned n4 = c.seg[s].n4;
        if (off < n4) {
            float4 v = ((const float4*)c.seg[s].s)[off];
            float h0,h1,h2,h3,l0,l1,l2,l3;
            split1(v.x,h0,l0); split1(v.y,h1,l1); split1(v.z,h2,l2); split1(v.w,h3,l3);
            ((uint2*)c.seg[s].h)[off] = make_uint2(pack2(h0,h1), pack2(h2,h3));
            ((uint2*)c.seg[s].l)[off] = make_uint2(pack2(l0,l1), pack2(l2,l3));
            return;
        }
        off -= n4;
    }
}

// ---------------- weight transpose + split (round-12) ----------------------
struct WT5 { const float* w[5]; __nv_bfloat16* h[5]; __nv_bfloat16* l[5]; };

__global__ __launch_bounds__(256) void convert_wT(WT5 wt)
{
    __shared__ float tile[32][33];
    const float* W = wt.w[blockIdx.z];
    __nv_bfloat16* Th = wt.h[blockIdx.z];
    __nv_bfloat16* Tl = wt.l[blockIdx.z];
    int bx = blockIdx.x, by = blockIdx.y;
    int tx = threadIdx.x & 31, ty = threadIdx.x >> 5;
#pragma unroll
    for (int i = 0; i < 4; i++)
        tile[ty + i * 8][tx] = W[(size_t)(by * 32 + ty + i * 8) * DM + bx * 32 + tx];
    __syncthreads();
#pragma unroll
    for (int i = 0; i < 4; i++) {
        float x = tile[tx][ty + i * 8];
        float h, l;
        split1(x, h, l);
        size_t o = (size_t)(bx * 32 + ty + i * 8) * DM + by * 32 + tx;
        Th[o] = __float2bfloat16_rn(h);
        Tl[o] = __float2bfloat16_rn(l);
    }
}

// ================= mma.sync bf16 3-pass GEMM (round-12 body) ===============
#define GSTRIDE 20
#define AW      (64*GSTRIDE)
#define BW      (128*GSTRIDE)
#define STW     (2*AW + 2*BW)
#define NSTAGE  3
#define GSMEM_BYTES (NSTAGE*STW*4)

struct GemmEnt {
    const __nv_bfloat16 *Ah, *Al, *Bth, *Btl;
    float* C;
    int M, rowsPer, mode;
};
struct Gemm4 { GemmEnt e[4]; };

static __device__ __forceinline__ void store_pair(
    float* C, int mode, int rowsPer, int r, int cn, float x, float y, int M)
{
    if (r >= M) return;
    float2 v = make_float2(x, y);
    if (mode == 0) {
        *(float2*)&C[(size_t)r * DM + cn] = v;
    } else {
        int b = r / rowsPer, rr = r - b * rowsPer;
        int h = cn >> 6, e = cn & 63;
        *(float2*)&C[((size_t)(b * H_ + h) * rowsPer + rr) * E_ + e] = v;
    }
}

static __device__ __forceinline__ void gemm_body(
    const GemmEnt Q, int m0, int n0)
{
    extern __shared__ uint32_t smw[];
    int tid = threadIdx.x, lane = tid & 31, wid = tid >> 5;
    int g = lane >> 2, t = lane & 3;
    int wm = wid & 1, wn = wid >> 1;

    float acc[2][4][4];
#pragma unroll
    for (int i = 0; i < 2; i++)
#pragma unroll
        for (int j = 0; j < 4; j++)
#pragma unroll
            for (int q = 0; q < 4; q++) acc[i][j][q] = 0.f;

    bool isA = tid < 128;
    int u = isA ? tid : (tid - 128);
    const __nv_bfloat16* segH[2];
    const __nv_bfloat16* segL[2];
    uint32_t segD[2];
    uint32_t loOff;
    int nseg;
    if (isA) {
        int row = u >> 1, half = u & 1;
        int rowC = row;
        if (m0 + rowC >= Q.M) { rowC = Q.M - 1 - m0; if (rowC < 0) rowC = 0; }
        segH[0] = Q.Ah + (size_t)(m0 + rowC) * DM + half * 16;
        segL[0] = Q.Al + (size_t)(m0 + rowC) * DM + half * 16;
        segD[0] = row * GSTRIDE + half * 8;
        loOff = AW; nseg = 1;
        segH[1] = segH[0]; segL[1] = segL[0]; segD[1] = segD[0];
    } else {
        loOff = BW; nseg = 2;
#pragma unroll
        for (int s = 0; s < 2; s++) {
            int unit = u + s * 128;
            int row = unit >> 1, half = unit & 1;
            segH[s] = Q.Bth + (size_t)(n0 + row) * DM + half * 16;
            segL[s] = Q.Btl + (size_t)(n0 + row) * DM + half * 16;
            segD[s] = 2 * AW + row * GSTRIDE + half * 8;
        }
    }
    uint32_t smb = smem_u32(smw);

    auto issue = [&](int ic, int stage) {
#pragma unroll
        for (int s = 0; s < 2; s++) {
            if (s >= nseg) break;
            const __nv_bfloat16* ph = segH[s] + ic * KCH;
            const __nv_bfloat16* pl = segL[s] + ic * KCH;
            uint32_t w = stage * STW + segD[s];
            cpasync16(smb + w * 4, ph);
            cpasync16(smb + (w + 4) * 4, ph + 8);
            cpasync16(smb + (w + loOff) * 4, pl);
            cpasync16(smb + (w + loOff + 4) * 4, pl + 8);
        }
    };

    int arow = wm * 32 + (lane & 7) + ((lane >> 3) & 1) * 8;
    int acol = (lane >> 4) * 4;
    int brow = wn * 32 + (lane & 7) + (lane >> 4) * 8;
    int bcol = ((lane >> 3) & 1) * 4;

    issue(0, 0); CP_COMMIT();
    issue(1, 1); CP_COMMIT();

    for (int ic = 0; ic < NCHUNK; ic++) {
        int buf = ic % NSTAGE;
        CP_WAIT1();
        __syncthreads();
        if (ic + 2 < NCHUNK) issue(ic + 2, (ic + 2) % NSTAGE);
        CP_COMMIT();

        uint32_t stage0 = smb + (buf * STW) * 4;
#pragma unroll
        for (int ks = 0; ks < 2; ks++) {
            uint32_t ah[2][4], al[2][4], bh[2][4], bl[2][4];
#pragma unroll
            for (int i = 0; i < 2; i++) {
                uint32_t ao = stage0 + ((arow + i * 16) * GSTRIDE + acol + ks * 8) * 4;
                ldsm4(ah[i], ao);
                ldsm4(al[i], ao + AW * 4);
            }
#pragma unroll
            for (int p = 0; p < 2; p++) {
                uint32_t bo = stage0 + (2 * AW + (brow + p * 16) * GSTRIDE + bcol + ks * 8) * 4;
                ldsm4(bh[p], bo);
                ldsm4(bl[p], bo + BW * 4);
            }
#pragma unroll
            for (int i = 0; i < 2; i++) {
#pragma unroll
                for (int p = 0; p < 2; p++) {
                    mma_bf16(acc[i][2*p],   ah[i], &bh[p][0]);
                    mma_bf16(acc[i][2*p+1], ah[i], &bh[p][2]);
                }
#pragma unroll
                for (int p = 0; p < 2; p++) {
                    mma_bf16(acc[i][2*p],   ah[i], &bl[p][0]);
                    mma_bf16(acc[i][2*p+1], ah[i], &bl[p][2]);
                }
#pragma unroll
                for (int p = 0; p < 2; p++) {
                    mma_bf16(acc[i][2*p],   al[i], &bh[p][0]);
                    mma_bf16(acc[i][2*p+1], al[i], &bh[p][2]);
                }
            }
        }
    }

#pragma unroll
    for (int i = 0; i < 2; i++) {
        int r = m0 + wm * 32 + i * 16 + g;
#pragma unroll
        for (int j = 0; j < 4; j++) {
            int cn = n0 + wn * 32 + j * 8 + t * 2;
            store_pair(Q.C, Q.mode, Q.rowsPer, r,     cn, acc[i][j][0], acc[i][j][1], Q.M);
            store_pair(Q.C, Q.mode, Q.rowsPer, r + 8, cn, acc[i][j][2], acc[i][j][3], Q.M);
        }
    }
}

__global__ __launch_bounds__(256, 2) void mma_gemm_multi(Gemm4 P)
{
    int bx = blockIdx.x;
    int z, xm;
    if (bx == 0) { z = 0; xm = 0; }
    else { z = 1 + ((bx - 1) >> 6); xm = (bx - 1) & 63; }
    gemm_body(P.e[z], xm * 64, blockIdx.y * 128);
}

__global__ __launch_bounds__(256, 2) void mma_gemm_one(GemmEnt Q)
{
    gemm_body(Q, blockIdx.x * 64, blockIdx.y * 128);
}

// ---------------- scores (round-12: grid (16,16), 128 thr) + fused mean ----
__global__ __launch_bounds__(128) void scores_kernel()
{
    int bh = blockIdx.x, stile = blockIdx.y;
    int tid = threadIdx.x;
    int s = stile * 128 + tid;

    __shared__ float csS[G_ * 64];
    __shared__ double sh[128];
    __shared__ int isLast;

    ((float4*)csS)[tid]       = ((const float4*)(g_cs + (size_t)bh * G_ * 64))[tid];
    ((float4*)csS)[tid + 128] = ((const float4*)(g_cs + (size_t)bh * G_ * 64))[tid + 128];
    __syncthreads();

    float kkr[64];
    const float4* kp = (const float4*)(g_kk + ((size_t)bh * S_ + s) * 64);
#pragma unroll
    for (int i = 0; i < 16; i++) {
        float4 v = kp[i];
        kkr[i*4] = v.x; kkr[i*4+1] = v.y; kkr[i*4+2] = v.z; kkr[i*4+3] = v.w;
    }

    double local = 0.0;
#pragma unroll
    for (int g = 0; g < G_; g++) {
        float d = 0.f;
#pragma unroll
        for (int e = 0; e < 64; e++) d += csS[g * 64 + e] * kkr[e];
        d *= 0.125f;
        g_scores[((size_t)(bh * G_ + g)) * S_ + s] = d;
        local += (double)d;
    }

    sh[tid] = local;
    __syncthreads();
    for (int o = 64; o; o >>= 1) {
        if (tid < o) sh[tid] += sh[tid + o];
        __syncthreads();
    }
    if (tid == 0) {
        g_partial[stile * G_ + bh] = sh[0];
        __threadfence();
        isLast = (atomicAdd(&g_ctr, 1) == 255);
    }
    __syncthreads();

    // deterministic fused mean: the single last-arriving block reduces all 256
    if (isLast) {
        __threadfence();
        sh[tid] = g_partial[tid] + g_partial[tid + 128];
        __syncthreads();
        for (int o = 64; o; o >>= 1) {
            if (tid < o) sh[tid] += sh[tid + o];
            __syncthreads();
        }
        if (tid == 0) {
            g_mean = (float)(sh[0] / (double)((size_t)NCHAIN * S_));
            g_ctr = 0;
        }
    }
}

__global__ __launch_bounds__(256) void wexp_kernel()
{
    int i = blockIdx.x * 256 + threadIdx.x;
    g_wexp[i] = expf(g_scores[i] - g_mean);
}

// ---------------- chunk sums (round-12) ----------------
__global__ __launch_bounds__(512) void chunk_sums_kernel()
{
    int bh = blockIdx.x, c = blockIdx.y;
    int tid = threadIdx.x;
    int g = tid >> 5, lane = tid & 31;

    __shared__ float kkS[CT * 64], vsS[CT * 64];
    ((float4*)kkS)[tid] = ((const float4*)(g_kk + ((size_t)bh * S_ + c * CT) * 64))[tid];
    ((float4*)vsS)[tid] = ((const float4*)(g_vs + ((size_t)bh * S_ + c * CT) * 64))[tid];

    int chain = bh * G_ + g;
    float wreg = g_wexp[(size_t)chain * S_ + c * CT + lane];
    __syncthreads();

    float nw = 0.f, ak0 = 0.f, ak1 = 0.f, av0 = 0.f, av1 = 0.f;
#pragma unroll
    for (int t = 0; t < CT; t++) {
        float w = __shfl_sync(0xffffffffu, wreg, t);
        nw += w;
        ak0 += w * kkS[t * 64 + lane];
        ak1 += w * kkS[t * 64 + lane + 32];
        av0 += w * vsS[t * 64 + lane];
        av1 += w * vsS[t * 64 + lane + 32];
    }
    float* op = g_chunk + ((size_t)chain * CH + c) * REC;
    op[1 + lane]  = ak0;
    op[33 + lane] = ak1;
    op[65 + lane] = av0;
    op[97 + lane] = av1;
    if (lane == 0) op[0] = nw;
}

// ---------------- chunk prefix (round-12 serial) ----------------
__global__ __launch_bounds__(160) void chunk_prefix_kernel()
{
    int chain = blockIdx.x;
    int t = threadIdx.x;
    if (t >= 129) return;
    float run = 0.f;
    for (int c = 0; c < CH; c++) {
        size_t idx = ((size_t)chain * CH + c) * REC + t;
        float v = g_chunk[idx];
        g_chunk[idx] = run;
        run += v;
    }
}

// ---------------- attn_scan v3 (round-12) ----------------
__global__ __launch_bounds__(512) void attn_scan_kernel()
{
    int bh = blockIdx.x, c = blockIdx.y;
    int tid = threadIdx.x;
    int g = tid >> 5, lane = tid & 31;

    __shared__ float kkS[CT * 64], vsS[CT * 64], qsS[CT * 64];
    __shared__ float Sv0[G_][64];
    __shared__ float Lg[CT][17];
    __shared__ float Nn[CT][17];
    __shared__ float Cc[CT][17];
    __shared__ float Wsm[G_][CT + 1];
    __shared__ float Mm[CT][CT + 1];

    const float* kkBase = g_kk + ((size_t)bh * S_ + c * CT) * E_;
    const float* vsBase = g_vs + ((size_t)bh * S_ + c * CT) * E_;
    const float* qsBase = g_qs + ((size_t)bh * S_ + c * CT) * E_;
    ((float4*)kkS)[tid] = ((const float4*)kkBase)[tid];
    ((float4*)vsS)[tid] = ((const float4*)vsBase)[tid];
    ((float4*)qsS)[tid] = ((const float4*)qsBase)[tid];

    const float* pf = g_chunk + ((size_t)(bh * G_ + g) * CH + c) * REC;
    float nw  = pf[0];
    float skA = pf[1 + lane];
    float skB = pf[33 + lane];
    Sv0[g][lane]      = pf[65 + lane];
    Sv0[g][lane + 32] = pf[97 + lane];
    float wchunk = g_wexp[(size_t)(bh * G_ + g) * S_ + c * CT + lane];
    Wsm[g][lane] = wchunk;
    __syncthreads();

    // phase 1: per-warp Sk scan + logits
#pragma unroll
    for (int t = 0; t < CT; t++) {
        float w = __shfl_sync(0xffffffffu, wchunk, t);
        nw  += w;
        skA += w * kkS[t * 64 + lane];
        skB += w * kkS[t * 64 + lane + 32];
        float d = qsS[t * 64 + lane] * skA + qsS[t * 64 + lane + 32] * skB;
#pragma unroll
        for (int o = 16; o; o >>= 1) d += __shfl_xor_sync(0xffffffffu, d, o);
        if (lane == 0) {
            float nwc = fmaxf(nw, 1e-8f);
            Lg[t][g] = d / nwc;
            Nn[t][g] = nwc;
        }
    }
    __syncthreads();

    // phase 2: softmax over g
    {
        int t2 = 2 * g + (lane >> 4);
        int gg = lane & 15;
        float x = Lg[t2][gg];
        float m = x;
#pragma unroll
        for (int o = 8; o; o >>= 1) m = fmaxf(m, __shfl_xor_sync(0xffffffffu, m, o));
        float e = expf(x - m);
        float ss = e;
#pragma unroll
        for (int o = 8; o; o >>= 1) ss += __shfl_xor_sync(0xffffffffu, ss, o);
        Cc[t2][gg] = (e / ss) / Nn[t2][gg];
    }
    __syncthreads();

    // phase 3a: M[t][tau]
#pragma unroll
    for (int r = 0; r < 2; r++) {
        int idx = tid + r * 512;
        int t = idx >> 5, tau = idx & 31;
        float m = 0.f;
#pragma unroll
        for (int gg = 0; gg < G_; gg++) m += Cc[t][gg] * Wsm[gg][tau];
        Mm[t][tau] = m;
    }
    __syncthreads();

    // phase 3b: out + bf16 split
    {
        int t  = tid >> 4;
        int eg = (tid & 15) * 4;
        float a0 = 0.f, a1 = 0.f, a2 = 0.f, a3 = 0.f;
#pragma unroll
        for (int gg = 0; gg < G_; gg++) {
            float cg = Cc[t][gg];
            float4 sv = *(const float4*)&Sv0[gg][eg];
            a0 += cg * sv.x; a1 += cg * sv.y; a2 += cg * sv.z; a3 += cg * sv.w;
        }
        for (int tau = 0; tau <= t; tau++) {
            float m = Mm[t][tau];
            float4 vv = *(const float4*)&vsS[tau * 64 + eg];
            a0 += m * vv.x; a1 += m * vv.y; a2 += m * vv.z; a3 += m * vv.w;
        }
        float h0,h1,h2,h3,l0,l1,l2,l3;
        split1(a0,h0,l0); split1(a1,h1,l1); split1(a2,h2,l2); split1(a3,h3,l3);
        int b = bh >> 3, h = bh & 7;
        size_t off = ((size_t)b * S_ + c * CT + t) * DM + h * 64 + eg;
        __nv_bfloat16* ahp = (__nv_bfloat16*)g_ah4;
        __nv_bfloat16* alp = (__nv_bfloat16*)g_al4;
        *(uint2*)(ahp + off) = make_uint2(pack2(h0,h1), pack2(h2,h3));
        *(uint2*)(alp + off) = make_uint2(pack2(l0,l1), pack2(l2,l3));
    }
}

// ---------------- launch ---------------------------------------------------
extern "C" void kernel_launch(void* const* d_in, const int* in_sizes, int n_in,
                              void* d_out, int out_size)
{
    const float* q   = (const float*)d_in[0];
    const float* k   = (const float*)d_in[1];
    const float* v   = (const float*)d_in[2];
    const float* ctx = (const float*)d_in[3];

    typedef __nv_bfloat16 bf;
    static float *p_qs = nullptr, *p_kk, *p_vs, *p_cs;
    static bf *qh,*ql,*kh,*kl,*vh,*vl,*ch,*cl;
    static bf *wqh,*wql,*wkh,*wkl,*wvh,*wvl,*woh,*wol,*wch,*wcl;
    static bf *ah,*al;
    if (!p_qs) {
        cudaGetSymbolAddress((void**)&p_qs,   g_qs);
        cudaGetSymbolAddress((void**)&p_kk,   g_kk);
        cudaGetSymbolAddress((void**)&p_vs,   g_vs);
        cudaGetSymbolAddress((void**)&p_cs,   g_cs);
        cudaGetSymbolAddress((void**)&qh, g_qh4);  cudaGetSymbolAddress((void**)&ql, g_ql4);
        cudaGetSymbolAddress((void**)&kh, g_kh4);  cudaGetSymbolAddress((void**)&kl, g_kl4);
        cudaGetSymbolAddress((void**)&vh, g_vh4);  cudaGetSymbolAddress((void**)&vl, g_vl4);
        cudaGetSymbolAddress((void**)&ch, g_ch4);  cudaGetSymbolAddress((void**)&cl, g_cl4);
        cudaGetSymbolAddress((void**)&wqh, g_wqh4); cudaGetSymbolAddress((void**)&wql, g_wql4);
        cudaGetSymbolAddress((void**)&wkh, g_wkh4); cudaGetSymbolAddress((void**)&wkl, g_wkl4);
        cudaGetSymbolAddress((void**)&wvh, g_wvh4); cudaGetSymbolAddress((void**)&wvl, g_wvl4);
        cudaGetSymbolAddress((void**)&woh, g_woh4); cudaGetSymbolAddress((void**)&wol, g_wol4);
        cudaGetSymbolAddress((void**)&wch, g_wch4); cudaGetSymbolAddress((void**)&wcl, g_wcl4);
        cudaGetSymbolAddress((void**)&ah, g_ah4);   cudaGetSymbolAddress((void**)&al, g_al4);
        cudaFuncSetAttribute(mma_gemm_multi, cudaFuncAttributeMaxDynamicSharedMemorySize, GSMEM_BYTES);
        cudaFuncSetAttribute(mma_gemm_one,   cudaFuncAttributeMaxDynamicSharedMemorySize, GSMEM_BYTES);
    }

    const unsigned N_BIG = (B_*S_*DM)/4;
    const unsigned N_CTX = (B_*G_*DM)/4;

    Conv4 c4;
    c4.seg[0] = { q,   qh, ql, N_BIG };
    c4.seg[1] = { k,   kh, kl, N_BIG };
    c4.seg[2] = { v,   vh, vl, N_BIG };
    c4.seg[3] = { ctx, ch, cl, N_CTX };
    unsigned total4 = 3 * N_BIG + N_CTX;
    convert_act<<<(total4 + 255) / 256, 256>>>(c4, total4);

    WT5 wt;
    wt.w[0] = (const float*)d_in[4]; wt.h[0] = wqh; wt.l[0] = wql;
    wt.w[1] = (const float*)d_in[5]; wt.h[1] = wkh; wt.l[1] = wkl;
    wt.w[2] = (const float*)d_in[6]; wt.h[2] = wvh; wt.l[2] = wvl;
    wt.w[3] = (const float*)d_in[7]; wt.h[3] = woh; wt.l[3] = wol;
    wt.w[4] = (const float*)d_in[8]; wt.h[4] = wch; wt.l[4] = wcl;
    convert_wT<<<dim3(16, 16, 5), 256>>>(wt);

    Gemm4 P;
    P.e[0] = { ch, cl, wch, wcl, p_cs, B_ * G_, G_, 1 };
    P.e[1] = { qh, ql, wqh, wql, p_qs, B_ * S_, S_, 1 };
    P.e[2] = { kh, kl, wkh, wkl, p_kk, B_ * S_, S_, 1 };
    P.e[3] = { vh, vl, wvh, wvl, p_vs, B_ * S_, S_, 1 };
    mma_gemm_multi<<<dim3(193, 4), 256, GSMEM_BYTES>>>(P);

    scores_kernel<<<dim3(G_, 16), 128>>>();
    wexp_kernel<<<(NCHAIN * S_) / 256, 256>>>();
    chunk_sums_kernel<<<dim3(G_, CH), 512>>>();
    chunk_prefix_kernel<<<NCHAIN, 160>>>();
    attn_scan_kernel<<<dim3(B_ * H_, CH), 512>>>();

    GemmEnt Qo = { ah, al, woh, wol, (float*)d_out, B_ * S_, S_, 0 };
    mma_gemm_one<<<dim3(64, 4), 256, GSMEM_BYTES>>>(Qo);
}